// round 12
// baseline (speedup 1.0000x reference)
#include <cuda_runtime.h>

// Problem constants (from reference: B, S, D = 16, 4096, 512)
#define BB 16
#define SS 4096
#define DD 512
#define GRID_FUSED 296   // 148 SMs x 2 blocks of 1024 thr — single co-resident wave

// Scratch + sync state (zero at load; reset in epilogue every launch).
__device__ int g_src[BB * SS];
__device__ int g_counts[BB];
__device__ int g_ready;
__device__ int g_exit;

static __device__ __forceinline__ int ld_acquire(const int* p) {
    int v;
    asm volatile("ld.acquire.gpu.b32 %0, [%1];" : "=r"(v) : "l"(p) : "memory");
    return v;
}

// ---------------------------------------------------------------------------
// Fused kernel, v3.
// Blocks 0..15: R4-shaped scan (1024 threads x 4 elems via float4), publish
//   g_src/g_counts, release single flag, THEN write mask rows (off the
//   critical path for the other 280 blocks).
// All 296 blocks: brief acquire-spin on the flag, then the warp-per-row
//   persistent gather (9472 warps; sits on the LTS cap ~136.5MB/6300B-per-cyc
//   ≈ 20.5us — untouched).
// Epilogue: last exiting block resets flags (replay-deterministic).
// ---------------------------------------------------------------------------
__global__ void __launch_bounds__(1024, 2)
fused_kernel(const float* __restrict__ x,
             const float4* __restrict__ probs4,
             const float4* __restrict__ uniform4,
             float* __restrict__ out_padded,
             float* __restrict__ out_mask,
             int max_length, int total_rows) {
    const int t = threadIdx.x;
    const int lane = t & 31;
    const int warp = t >> 5;
    __shared__ int s_counts[BB];

    if (blockIdx.x < BB) {
        const int b = blockIdx.x;
        const int idx4 = b * (SS / 4) + t;

        float4 p = probs4[idx4];
        float4 u = uniform4[idx4];

        int keep[4];
        keep[0] = (u.x >= p.x) ? 1 : 0;
        keep[1] = (u.y >= p.y) ? 1 : 0;
        keep[2] = (u.z >= p.z) ? 1 : 0;
        keep[3] = (u.w >= p.w) ? 1 : 0;
        int local = keep[0] + keep[1] + keep[2] + keep[3];

        int v = local;
#pragma unroll
        for (int o = 1; o < 32; o <<= 1) {
            int uu = __shfl_up_sync(0xffffffffu, v, o);
            if (lane >= o) v += uu;
        }
        __shared__ int warp_sums[32];
        __shared__ int s_total;
        if (lane == 31) warp_sums[warp] = v;
        __syncthreads();
        if (warp == 0) {
            int w = warp_sums[lane];
#pragma unroll
            for (int o = 1; o < 32; o <<= 1) {
                int uu = __shfl_up_sync(0xffffffffu, w, o);
                if (lane >= o) w += uu;
            }
            warp_sums[lane] = w;
            if (lane == 31) s_total = w;
        }
        __syncthreads();

        int excl = v - local + (warp > 0 ? warp_sums[warp - 1] : 0);

        int r = excl;
#pragma unroll
        for (int i = 0; i < 4; i++) {
            if (keep[i]) {
                g_src[b * SS + r] = t * 4 + i;
                r++;
            }
        }

        const int count = s_total;
        if (t == 0) g_counts[b] = count;

        // Publish this batch's scan (single-flag release, R8-proven).
        __syncthreads();
        if (t == 0) {
            __threadfence();
            atomicAdd(&g_ready, 1);
        }

        // Mask row AFTER the release — off the other blocks' critical path.
        float* mrow = out_mask + (long long)b * max_length;
        for (int j = t; j < max_length; j += 1024) {
            mrow[j] = (j < count) ? 1.0f : 0.0f;
        }
    }

    // ---------------- barrier: all 16 scans published ----------------
    if (t == 0) {
        while (ld_acquire(&g_ready) < BB) __nanosleep(64);
    }
    __syncthreads();
    if (t < BB) s_counts[t] = g_counts[t];
    __syncthreads();

    // ---------------- persistent gather (R4 body, LTS-cap bound) ----------------
    const int gw = blockIdx.x * 32 + warp;   // global warp id
    const int nw = gridDim.x * 32;           // 9472 total warps

    for (int row = gw; row < total_rows; row += nw) {
        const int b = row / max_length;
        const int j = row - b * max_length;

        float4* dst = reinterpret_cast<float4*>(out_padded + (long long)row * DD);

        if (j < s_counts[b]) {
            const int s = __ldg(&g_src[b * SS + j]);
            const float4* src = reinterpret_cast<const float4*>(
                x + ((long long)b * SS + s) * DD);
            float4 v0 = __ldcg(src + lane);
            float4 v1 = __ldcg(src + lane + 32);
            float4 v2 = __ldcg(src + lane + 64);
            float4 v3 = __ldcg(src + lane + 96);
            __stcs(dst + lane,      v0);
            __stcs(dst + lane + 32, v1);
            __stcs(dst + lane + 64, v2);
            __stcs(dst + lane + 96, v3);
        } else {
            const float4 z = make_float4(0.f, 0.f, 0.f, 0.f);
            __stcs(dst + lane,      z);
            __stcs(dst + lane + 32, z);
            __stcs(dst + lane + 64, z);
            __stcs(dst + lane + 96, z);
        }
    }

    // ---------------- epilogue: reset sync state for next replay ----------------
    __syncthreads();
    if (t == 0) {
        int old = atomicAdd(&g_exit, 1);
        if (old == (int)gridDim.x - 1) {
            g_ready = 0;
            g_exit = 0;
        }
    }
}

// ---------------------------------------------------------------------------
// Launch: out_size = B*ML*(D+1)  =>  ML = out_size / (B*(D+1))
// ---------------------------------------------------------------------------
extern "C" void kernel_launch(void* const* d_in, const int* in_sizes, int n_in,
                              void* d_out, int out_size) {
    const float* x       = (const float*)d_in[0];
    const float* probs   = (const float*)d_in[1];
    const float* uniform = (const float*)d_in[2];
    float* out = (float*)d_out;

    const int max_length = out_size / (BB * (DD + 1));
    float* out_mask = out + (long long)BB * max_length * DD;
    const int total_rows = BB * max_length;

    fused_kernel<<<GRID_FUSED, 1024>>>(x, (const float4*)probs,
                                       (const float4*)uniform,
                                       out, out_mask, max_length, total_rows);
}

// round 13
// speedup vs baseline: 1.1115x; 1.1115x over previous
#include <cuda_runtime.h>

// Problem constants (from reference: B, S, D = 16, 4096, 512)
#define BB 16
#define SS 4096
#define DD 512
#define SLICES 9   // gather blocks per batch; each rescans its batch (32KB)

// ---------------------------------------------------------------------------
// Sync-free fused kernel. Grid = (SLICES, BB), 1024 threads.
// Phase A: block (slice, b) redundantly scans batch b's keep flags into an
//   SMEM rank table (stable block-wide exclusive scan, 4 elems/thread).
//   No global scratch, no inter-block communication, no barriers beyond
//   one __syncthreads.
// Phase B: block gathers its contiguous slice of batch b's output rows,
//   warp-per-row, 4x LDG.128 front-batched -> 4x STG.128; padding rows
//   write zeros; lane 0 writes the mask element. The gather sits on the
//   LTS cap (~136.5MB compulsory + 4.6MB rescan redundancy).
// ---------------------------------------------------------------------------
__global__ void __launch_bounds__(1024)
fused_kernel(const float* __restrict__ x,
             const float4* __restrict__ probs4,
             const float4* __restrict__ uniform4,
             float* __restrict__ out_padded,
             float* __restrict__ out_mask,
             int max_length) {
    const int b     = blockIdx.y;
    const int slice = blockIdx.x;
    const int t     = threadIdx.x;
    const int lane  = t & 31;
    const int warp  = t >> 5;

    __shared__ int s_src[SS];      // rank -> source element index (16KB)
    __shared__ int warp_sums[32];
    __shared__ int s_count;

    // ---------------- Phase A: scan batch b into SMEM ----------------
    const int idx4 = b * (SS / 4) + t;
    float4 p = probs4[idx4];
    float4 u = uniform4[idx4];

    int keep[4];
    keep[0] = (u.x >= p.x) ? 1 : 0;
    keep[1] = (u.y >= p.y) ? 1 : 0;
    keep[2] = (u.z >= p.z) ? 1 : 0;
    keep[3] = (u.w >= p.w) ? 1 : 0;
    const int local = keep[0] + keep[1] + keep[2] + keep[3];

    int v = local;
#pragma unroll
    for (int o = 1; o < 32; o <<= 1) {
        int uu = __shfl_up_sync(0xffffffffu, v, o);
        if (lane >= o) v += uu;
    }
    if (lane == 31) warp_sums[warp] = v;
    __syncthreads();
    if (warp == 0) {
        int w = warp_sums[lane];
#pragma unroll
        for (int o = 1; o < 32; o <<= 1) {
            int uu = __shfl_up_sync(0xffffffffu, w, o);
            if (lane >= o) w += uu;
        }
        warp_sums[lane] = w;
        if (lane == 31) s_count = w;
    }
    __syncthreads();

    const int excl = v - local + (warp > 0 ? warp_sums[warp - 1] : 0);

    int r = excl;
#pragma unroll
    for (int i = 0; i < 4; i++) {
        if (keep[i]) {
            s_src[r] = t * 4 + i;
            r++;
        }
    }
    __syncthreads();

    // ---------------- Phase B: gather this block's row slice ----------------
    const int count = s_count;
    const int chunk = (max_length + SLICES - 1) / SLICES;
    const int jbeg  = slice * chunk;
    int jend = jbeg + chunk;
    if (jend > max_length) jend = max_length;

    for (int j = jbeg + warp; j < jend; j += 32) {
        const long long row = (long long)b * max_length + j;
        float4* dst = reinterpret_cast<float4*>(out_padded + row * DD);

        if (j < count) {
            const int s = s_src[j];
            const float4* src = reinterpret_cast<const float4*>(
                x + ((long long)b * SS + s) * DD);
            float4 v0 = __ldcg(src + lane);
            float4 v1 = __ldcg(src + lane + 32);
            float4 v2 = __ldcg(src + lane + 64);
            float4 v3 = __ldcg(src + lane + 96);
            __stcs(dst + lane,      v0);
            __stcs(dst + lane + 32, v1);
            __stcs(dst + lane + 64, v2);
            __stcs(dst + lane + 96, v3);
        } else {
            const float4 z = make_float4(0.f, 0.f, 0.f, 0.f);
            __stcs(dst + lane,      z);
            __stcs(dst + lane + 32, z);
            __stcs(dst + lane + 64, z);
            __stcs(dst + lane + 96, z);
        }

        if (lane == 0) {
            out_mask[row] = (j < count) ? 1.0f : 0.0f;
        }
    }
}

// ---------------------------------------------------------------------------
// Launch: out_size = B*ML*(D+1)  =>  ML = out_size / (B*(D+1))
// Single kernel node, no device-side synchronization anywhere.
// ---------------------------------------------------------------------------
extern "C" void kernel_launch(void* const* d_in, const int* in_sizes, int n_in,
                              void* d_out, int out_size) {
    const float* x       = (const float*)d_in[0];
    const float* probs   = (const float*)d_in[1];
    const float* uniform = (const float*)d_in[2];
    float* out = (float*)d_out;

    const int max_length = out_size / (BB * (DD + 1));
    float* out_mask = out + (long long)BB * max_length * DD;

    dim3 grid(SLICES, BB);
    fused_kernel<<<grid, 1024>>>(x, (const float4*)probs,
                                 (const float4*)uniform,
                                 out, out_mask, max_length);
}